// round 12
// baseline (speedup 1.0000x reference)
#include <cuda_runtime.h>
#include <cuda_bf16.h>

#define G 8
#define THREADS 256
#define NBLK (8192 / G)

typedef unsigned long long f32x2_t;

__device__ __forceinline__ f32x2_t fma2(f32x2_t a, f32x2_t b, f32x2_t c) {
    f32x2_t d;
    asm("fma.rn.f32x2 %0, %1, %2, %3;" : "=l"(d) : "l"(a), "l"(b), "l"(c));
    return d;
}
__device__ __forceinline__ f32x2_t pk2(float lo, float hi) {
    f32x2_t d;
    asm("mov.b64 %0, {%1, %2};" : "=l"(d) : "f"(lo), "f"(hi));
    return d;
}
__device__ __forceinline__ float2 upk(f32x2_t d) {
    float2 v;
    asm("mov.b64 {%0, %1}, %2;" : "=f"(v.x), "=f"(v.y) : "l"(d));
    return v;
}
__device__ __forceinline__ f32x2_t dup2(float v) { return pk2(v, v); }

// Binarized weights, repacked (16B-aligned).
__device__ __align__(16) float g_w1c[3 * 25 * 8];       // [cin][k][c8] (c<6 used)
__device__ __align__(16) float g_w2c[4 * 6 * 25 * 4];   // [cq][cin][k][c4]
__device__ __align__(16) float g_fw1t[400 * 120];       // [k][j]
__device__ __align__(16) float g_fw2t[120 * 84];        // [k][j]
__device__ __align__(16) float g_fw3t[84 * 10];         // [k][j]

__global__ void binarize_kernel(const float* __restrict__ w1,
                                const float* __restrict__ w2,
                                const float* __restrict__ fw1,
                                const float* __restrict__ fw2,
                                const float* __restrict__ fw3) {
    __shared__ float red[256];
    int t = threadIdx.x;
    const float* src = nullptr;
    int n = 0;
    switch (blockIdx.x) {
        case 0: src = w1;  n = 450;   break;
        case 1: src = w2;  n = 2400;  break;
        case 2: src = fw1; n = 48000; break;
        case 3: src = fw2; n = 10080; break;
        case 4: src = fw3; n = 840;   break;
    }
    float s = 0.0f;
    for (int i = t; i < n; i += 256) s += fabsf(src[i]);
    red[t] = s;
    __syncthreads();
    for (int o = 128; o > 0; o >>= 1) {
        if (t < o) red[t] += red[t + o];
        __syncthreads();
    }
    float scale = red[0] / (float)n;

    switch (blockIdx.x) {
        case 0:  // w1[o][cin][5][5] -> [cin][k][c8]
            for (int i = t; i < n; i += 256) {
                int o = i / 75, rem = i % 75, cin = rem / 25, k = rem % 25;
                g_w1c[(cin * 25 + k) * 8 + o] = (src[i] >= 0.0f) ? scale : -scale;
            }
            break;
        case 1:  // w2[o][cin][5][5] -> [cq][cin][k][c4]
            for (int i = t; i < n; i += 256) {
                int o = i / 150, rem = i % 150, cin = rem / 25, k = rem % 25;
                int cq = o >> 2, cl = o & 3;
                g_w2c[((cq * 6 + cin) * 25 + k) * 4 + cl] = (src[i] >= 0.0f) ? scale : -scale;
            }
            break;
        case 2:  // fc1 [120][400] -> [400][120]
            for (int i = t; i < n; i += 256) {
                int r = i / 400, c = i % 400;
                g_fw1t[c * 120 + r] = (src[i] >= 0.0f) ? scale : -scale;
            }
            break;
        case 3:  // fc2 [84][120] -> [120][84]
            for (int i = t; i < n; i += 256) {
                int r = i / 120, c = i % 120;
                g_fw2t[c * 84 + r] = (src[i] >= 0.0f) ? scale : -scale;
            }
            break;
        case 4:  // fc3 [10][84] -> [84][10]
            for (int i = t; i < n; i += 256) {
                int r = i / 84, c = i % 84;
                g_fw3t[c * 10 + r] = (src[i] >= 0.0f) ? scale : -scale;
            }
            break;
    }
}

extern __shared__ float smem[];

__global__ void __launch_bounds__(THREADS, 2)
fused_kernel(const float* __restrict__ x,
             const float* __restrict__ b1, const float* __restrict__ b2,
             const float* __restrict__ fb1, const float* __restrict__ fb2,
             const float* __restrict__ fb3,
             float* __restrict__ out) {
    // All activations stored as image-PAIR interleaved float2 (imgA, imgB).
    float2* const p1p = (float2*)smem;        // 4 pairs * 6c * 196    = 4704 float2
    float2* const h2p = p1p + 4704;           // 4 * 400               = 1600 float2
    float2* const a1p = h2p + 1600;           // 4 * 120               = 480 float2
    float2* const a2p = a1p + 480;            // 4 * 84                = 336 float2
    float* const w1s = (float*)(a2p + 336);   // 600
    float* const w2s = w1s + 600;             // 2400
    float* const b1s = w2s + 2400;            // 6
    float* const b2s = b1s + 6;               // 16

    const int tid = threadIdx.x;
    const int img0 = blockIdx.x * G;

    for (int i = tid; i < 600; i += THREADS)  w1s[i] = g_w1c[i];
    for (int i = tid; i < 2400; i += THREADS) w2s[i] = g_w2c[i];
    if (tid < 6)  b1s[tid] = b1[tid];
    if (tid < 16) b2s[tid] = b2[tid];
    __syncthreads();

    // ---- conv1 + relu + pool : thread = (img-pair, pooled px) ----
    for (int s = tid; s < 4 * 196; s += THREADS) {
        int ip = s / 196, p = s % 196;
        int py = p / 14, px = p % 14;
        const float* xa = x + (size_t)(img0 + ip * 2) * 3072 + py * 64 + px * 2;
        const float* xb = xa + 3072;

        #pragma unroll 1
        for (int cg = 0; cg < 2; cg++) {            // channel groups {0-2},{3-5}
            f32x2_t acc[3][4];
            #pragma unroll
            for (int c = 0; c < 3; c++)
                acc[c][0] = acc[c][1] = acc[c][2] = acc[c][3] = 0ULL;

            #pragma unroll 1
            for (int cin = 0; cin < 3; cin++) {
                f32x2_t wp[6][6];
                const float* ia = xa + cin * 1024;
                const float* ib = xb + cin * 1024;
                #pragma unroll
                for (int r = 0; r < 6; r++) {
                    float2 a0 = __ldg((const float2*)(ia + r * 32));
                    float2 a1 = __ldg((const float2*)(ia + r * 32 + 2));
                    float2 a2 = __ldg((const float2*)(ia + r * 32 + 4));
                    float2 c0 = __ldg((const float2*)(ib + r * 32));
                    float2 c1 = __ldg((const float2*)(ib + r * 32 + 2));
                    float2 c2 = __ldg((const float2*)(ib + r * 32 + 4));
                    wp[r][0] = pk2(a0.x, c0.x); wp[r][1] = pk2(a0.y, c0.y);
                    wp[r][2] = pk2(a1.x, c1.x); wp[r][3] = pk2(a1.y, c1.y);
                    wp[r][4] = pk2(a2.x, c2.x); wp[r][5] = pk2(a2.y, c2.y);
                }
                const float* wb = w1s + cin * 200 + cg * 3;
                #pragma unroll
                for (int k = 0; k < 25; k++) {
                    int ky = k / 5, kx = k % 5;
                    f32x2_t w0 = dup2(wb[k * 8 + 0]);
                    f32x2_t w1 = dup2(wb[k * 8 + 1]);
                    f32x2_t w2 = dup2(wb[k * 8 + 2]);
                    #pragma unroll
                    for (int q = 0; q < 4; q++) {
                        int qy = q >> 1, qx = q & 1;
                        f32x2_t wv = wp[ky + qy][kx + qx];
                        acc[0][q] = fma2(w0, wv, acc[0][q]);
                        acc[1][q] = fma2(w1, wv, acc[1][q]);
                        acc[2][q] = fma2(w2, wv, acc[2][q]);
                    }
                }
            }
            #pragma unroll
            for (int c = 0; c < 3; c++) {
                int ch = cg * 3 + c;
                float2 q0 = upk(acc[c][0]), q1 = upk(acc[c][1]);
                float2 q2 = upk(acc[c][2]), q3 = upk(acc[c][3]);
                float bb = b1s[ch];
                float2 v;
                v.x = fmaxf(fmaxf(fmaxf(q0.x, q1.x), fmaxf(q2.x, q3.x)) + bb, 0.0f);
                v.y = fmaxf(fmaxf(fmaxf(q0.y, q1.y), fmaxf(q2.y, q3.y)) + bb, 0.0f);
                p1p[(ip * 6 + ch) * 196 + p] = v;
            }
        }
    }
    __syncthreads();

    // ---- conv2 + relu + pool : thread = (img-pair, co-pair, pooled px) ----
    for (int s = tid; s < 800; s += THREADS) {
        int ip = s / 200, r = s % 200;
        int cop = r / 25, p = r % 25;           // cop 0..7 -> channels 2*cop,2*cop+1
        int py = p / 5, px = p % 5;
        int cq = cop >> 1, clb = (cop & 1) * 2;
        f32x2_t acc[2][4];
        #pragma unroll
        for (int c = 0; c < 2; c++)
            acc[c][0] = acc[c][1] = acc[c][2] = acc[c][3] = 0ULL;

        #pragma unroll 1
        for (int cin = 0; cin < 6; cin++) {
            f32x2_t wp[6][6];
            const float2* ibp = p1p + (ip * 6 + cin) * 196 + py * 28 + px * 2;
            #pragma unroll
            for (int rr = 0; rr < 6; rr++) {
                ulonglong2 u0 = *(const ulonglong2*)(ibp + rr * 14);
                ulonglong2 u1 = *(const ulonglong2*)(ibp + rr * 14 + 2);
                ulonglong2 u2 = *(const ulonglong2*)(ibp + rr * 14 + 4);
                wp[rr][0] = u0.x; wp[rr][1] = u0.y;
                wp[rr][2] = u1.x; wp[rr][3] = u1.y;
                wp[rr][4] = u2.x; wp[rr][5] = u2.y;
            }
            const float* wb = w2s + (cq * 6 + cin) * 100 + clb;
            #pragma unroll
            for (int k = 0; k < 25; k++) {
                int ky = k / 5, kx = k % 5;
                f32x2_t w0 = dup2(wb[k * 4 + 0]);
                f32x2_t w1 = dup2(wb[k * 4 + 1]);
                #pragma unroll
                for (int q = 0; q < 4; q++) {
                    int qy = q >> 1, qx = q & 1;
                    f32x2_t wv = wp[ky + qy][kx + qx];
                    acc[0][q] = fma2(w0, wv, acc[0][q]);
                    acc[1][q] = fma2(w1, wv, acc[1][q]);
                }
            }
        }
        #pragma unroll
        for (int c = 0; c < 2; c++) {
            int ch = cop * 2 + c;
            float2 q0 = upk(acc[c][0]), q1 = upk(acc[c][1]);
            float2 q2 = upk(acc[c][2]), q3 = upk(acc[c][3]);
            float bb = b2s[ch];
            float2 v;
            v.x = fmaxf(fmaxf(fmaxf(q0.x, q1.x), fmaxf(q2.x, q3.x)) + bb, 0.0f);
            v.y = fmaxf(fmaxf(fmaxf(q0.y, q1.y), fmaxf(q2.y, q3.y)) + bb, 0.0f);
            h2p[ip * 400 + ch * 25 + p] = v;    // NCHW-flatten order per image
        }
    }
    __syncthreads();

    // ---- fc1: thread = (j-pair 0..59, img-pair 0..3), relu ----
    if (tid < 240) {
        int ip = tid & 3, jp = tid >> 2;
        int j0 = jp * 2;
        const float2* hp = h2p + ip * 400;
        f32x2_t acc0 = 0ULL, acc1 = 0ULL;
        #pragma unroll 4
        for (int k = 0; k < 400; k++) {
            f32x2_t ap = *(const f32x2_t*)(hp + k);
            float2 w = *(const float2*)(g_fw1t + k * 120 + j0);
            acc0 = fma2(dup2(w.x), ap, acc0);
            acc1 = fma2(dup2(w.y), ap, acc1);
        }
        float2 r0 = upk(acc0), r1 = upk(acc1);
        float bb0 = fb1[j0], bb1 = fb1[j0 + 1];
        float2 o0, o1;
        o0.x = fmaxf(r0.x + bb0, 0.0f); o0.y = fmaxf(r0.y + bb0, 0.0f);
        o1.x = fmaxf(r1.x + bb1, 0.0f); o1.y = fmaxf(r1.y + bb1, 0.0f);
        a1p[ip * 120 + j0]     = o0;
        a1p[ip * 120 + j0 + 1] = o1;
    }
    __syncthreads();

    // ---- fc2: thread = (j-pair 0..41, img-pair 0..3), relu ----
    if (tid < 168) {
        int ip = tid & 3, jp = tid >> 2;
        int j0 = jp * 2;
        const float2* hp = a1p + ip * 120;
        f32x2_t acc0 = 0ULL, acc1 = 0ULL;
        #pragma unroll 4
        for (int k = 0; k < 120; k++) {
            f32x2_t ap = *(const f32x2_t*)(hp + k);
            float2 w = *(const float2*)(g_fw2t + k * 84 + j0);
            acc0 = fma2(dup2(w.x), ap, acc0);
            acc1 = fma2(dup2(w.y), ap, acc1);
        }
        float2 r0 = upk(acc0), r1 = upk(acc1);
        float bb0 = fb2[j0], bb1 = fb2[j0 + 1];
        float2 o0, o1;
        o0.x = fmaxf(r0.x + bb0, 0.0f); o0.y = fmaxf(r0.y + bb0, 0.0f);
        o1.x = fmaxf(r1.x + bb1, 0.0f); o1.y = fmaxf(r1.y + bb1, 0.0f);
        a2p[ip * 84 + j0]     = o0;
        a2p[ip * 84 + j0 + 1] = o1;
    }
    __syncthreads();

    // ---- fc3: [84] -> [10] ----
    if (tid < G * 10) {
        int g = tid / 10, j = tid % 10;
        const float* ag = (const float*)(a2p + (g >> 1) * 84);
        int im = g & 1;
        float s0 = 0.f, s1 = 0.f;
        #pragma unroll 6
        for (int k = 0; k < 84; k += 2) {
            s0 = fmaf(ag[k * 2 + im],       g_fw3t[(k)     * 10 + j], s0);
            s1 = fmaf(ag[(k + 1) * 2 + im], g_fw3t[(k + 1) * 10 + j], s1);
        }
        out[(size_t)(img0 + g) * 10 + j] = fb3[j] + s0 + s1;
    }
}

extern "C" void kernel_launch(void* const* d_in, const int* in_sizes, int n_in,
                              void* d_out, int out_size) {
    const float* x   = (const float*)d_in[0];
    const float* w1  = (const float*)d_in[1];
    const float* b1  = (const float*)d_in[2];
    const float* w2  = (const float*)d_in[3];
    const float* b2  = (const float*)d_in[4];
    const float* fw1 = (const float*)d_in[5];
    const float* fb1 = (const float*)d_in[6];
    const float* fw2 = (const float*)d_in[7];
    const float* fb2 = (const float*)d_in[8];
    const float* fw3 = (const float*)d_in[9];
    const float* fb3 = (const float*)d_in[10];
    float* out = (float*)d_out;

    // smem: (4704+1600+480+336)*2 + 600+2400+6+16 = 17262 floats = 69,048 B
    const int smem_floats = (4704 + 1600 + 480 + 336) * 2 + 600 + 2400 + 6 + 16;
    const int smem_bytes = smem_floats * (int)sizeof(float);
    cudaFuncSetAttribute(fused_kernel, cudaFuncAttributeMaxDynamicSharedMemorySize,
                         smem_bytes);

    binarize_kernel<<<5, 256>>>(w1, w2, fw1, fw2, fw3);
    fused_kernel<<<NBLK, THREADS, smem_bytes>>>(x, b1, b2, fb1, fb2, fb3, out);
}

// round 14
// speedup vs baseline: 1.4801x; 1.4801x over previous
#include <cuda_runtime.h>
#include <cuda_bf16.h>

#define G 8
#define THREADS 256
#define NBLK (8192 / G)

// Conv weights repacked with scale baked in; FC weights used raw + scale.
__device__ __align__(16) float g_w1c[3 * 25 * 8];       // [cin][k][c8] (c<6 used)
__device__ __align__(16) float g_w2c[4 * 6 * 25 * 4];   // [cq][cin][k][c4]
__device__ float g_fscale[3];                           // fc1, fc2, fc3 scales

__global__ void binarize_kernel(const float* __restrict__ w1,
                                const float* __restrict__ w2,
                                const float* __restrict__ fw1,
                                const float* __restrict__ fw2,
                                const float* __restrict__ fw3) {
    __shared__ float red[256];
    int t = threadIdx.x;
    const float* src = nullptr;
    int n = 0;
    switch (blockIdx.x) {
        case 0: src = w1;  n = 450;   break;
        case 1: src = w2;  n = 2400;  break;
        case 2: src = fw1; n = 48000; break;
        case 3: src = fw2; n = 10080; break;
        case 4: src = fw3; n = 840;   break;
    }
    float s = 0.0f;
    for (int i = t; i < n; i += 256) s += fabsf(src[i]);
    red[t] = s;
    __syncthreads();
    for (int o = 128; o > 0; o >>= 1) {
        if (t < o) red[t] += red[t + o];
        __syncthreads();
    }
    float scale = red[0] / (float)n;

    switch (blockIdx.x) {
        case 0:  // w1[o][cin][5][5] -> [cin][k][c8], value = +-scale
            for (int i = t; i < n; i += 256) {
                int o = i / 75, rem = i % 75, cin = rem / 25, k = rem % 25;
                g_w1c[(cin * 25 + k) * 8 + o] = (src[i] >= 0.0f) ? scale : -scale;
            }
            break;
        case 1:  // w2[o][cin][5][5] -> [cq][cin][k][c4]
            for (int i = t; i < n; i += 256) {
                int o = i / 150, rem = i % 150, cin = rem / 25, k = rem % 25;
                int cq = o >> 2, cl = o & 3;
                g_w2c[((cq * 6 + cin) * 25 + k) * 4 + cl] = (src[i] >= 0.0f) ? scale : -scale;
            }
            break;
        case 2: if (t == 0) g_fscale[0] = scale; break;
        case 3: if (t == 0) g_fscale[1] = scale; break;
        case 4: if (t == 0) g_fscale[2] = scale; break;
    }
}

extern __shared__ float smem[];

// One ky-row of conv1: 5 kx taps, 6 channels; TOP/BOT are 6-wide row regs.
#define CONV1_KY(TOP, BOT, KY)                                                 \
    {                                                                          \
        _Pragma("unroll")                                                      \
        for (int kx = 0; kx < 5; kx++) {                                       \
            const int k = (KY) * 5 + kx;                                       \
            float4 wv = *(const float4*)(wb + k * 8);                          \
            float2 wv2 = *(const float2*)(wb + k * 8 + 4);                     \
            float wc[6] = {wv.x, wv.y, wv.z, wv.w, wv2.x, wv2.y};              \
            _Pragma("unroll")                                                  \
            for (int c = 0; c < 6; c++) {                                      \
                acc[c][0] = fmaf(wc[c], TOP[kx],     acc[c][0]);               \
                acc[c][1] = fmaf(wc[c], TOP[kx + 1], acc[c][1]);               \
                acc[c][2] = fmaf(wc[c], BOT[kx],     acc[c][2]);               \
                acc[c][3] = fmaf(wc[c], BOT[kx + 1], acc[c][3]);               \
            }                                                                  \
        }                                                                      \
    }

// Load 6 floats from an 8B-aligned address (px*2 is always even).
#define LOAD_ROW6(DST, PTR)                                                    \
    {                                                                          \
        float2 va = __ldg((const float2*)(PTR));                               \
        float2 vb = __ldg((const float2*)((PTR) + 2));                         \
        float2 vc = __ldg((const float2*)((PTR) + 4));                         \
        DST[0] = va.x; DST[1] = va.y; DST[2] = vb.x;                           \
        DST[3] = vb.y; DST[4] = vc.x; DST[5] = vc.y;                           \
    }

__global__ void __launch_bounds__(THREADS, 3)
fused_kernel(const float* __restrict__ x,
             const float* __restrict__ fw1, const float* __restrict__ fw2,
             const float* __restrict__ fw3,
             const float* __restrict__ b1, const float* __restrict__ b2,
             const float* __restrict__ fb1, const float* __restrict__ fb2,
             const float* __restrict__ fb3,
             float* __restrict__ out) {
    float* const p1  = smem;                  // G*1176  [g][c][14*14]
    float* const h2  = p1 + G * 1176;         // G*400
    float* const a1  = h2 + G * 400;          // G*120
    float* const a2  = a1 + G * 120;          // G*84
    float* const w1s = a2 + G * 84;           // 600
    float* const w2s = w1s + 600;             // 2400
    float* const b1s = w2s + 2400;            // 6
    float* const b2s = b1s + 6;               // 16

    const int tid = threadIdx.x;
    const int img0 = blockIdx.x * G;

    for (int i = tid; i < 600; i += THREADS)  w1s[i] = g_w1c[i];
    for (int i = tid; i < 2400; i += THREADS) w2s[i] = g_w2c[i];
    if (tid < 6)  b1s[tid] = b1[tid];
    if (tid < 16) b2s[tid] = b2[tid];
    __syncthreads();

    // ---- conv1 + relu + pool : thread = (g, pooled px); rolling 2-row window
    for (int s = tid; s < G * 196; s += THREADS) {
        int g = s / 196, p = s % 196;
        int py = p / 14, px = p % 14;
        const float* xg = x + (size_t)(img0 + g) * 3072 + py * 64 + px * 2;
        float acc[6][4];
        #pragma unroll
        for (int c = 0; c < 6; c++)
            acc[c][0] = acc[c][1] = acc[c][2] = acc[c][3] = 0.0f;

        #pragma unroll 1
        for (int cin = 0; cin < 3; cin++) {
            const float* ib = xg + cin * 1024;
            const float* wb = w1s + cin * 200;
            float rA[6], rB[6];
            LOAD_ROW6(rA, ib);            // row 0
            LOAD_ROW6(rB, ib + 32);       // row 1
            CONV1_KY(rA, rB, 0); LOAD_ROW6(rA, ib + 64);    // row 2
            CONV1_KY(rB, rA, 1); LOAD_ROW6(rB, ib + 96);    // row 3
            CONV1_KY(rA, rB, 2); LOAD_ROW6(rA, ib + 128);   // row 4
            CONV1_KY(rB, rA, 3); LOAD_ROW6(rB, ib + 160);   // row 5
            CONV1_KY(rA, rB, 4);
        }
        #pragma unroll
        for (int c = 0; c < 6; c++) {
            float m = fmaxf(fmaxf(acc[c][0], acc[c][1]), fmaxf(acc[c][2], acc[c][3]));
            p1[(g * 6 + c) * 196 + p] = fmaxf(m + b1s[c], 0.0f);
        }
    }
    __syncthreads();

    // ---- conv2 + relu + pool : thread = (g, cq, pooled p), 4-channel quad
    for (int s = tid; s < G * 100; s += THREADS) {
        int g = s / 100, r = s % 100;
        int cq = r / 25, p = r % 25;
        int py = p / 5, px = p % 5;
        const float* inb = p1 + g * 1176 + (py * 2) * 14 + px * 2;
        float acc[4][4];
        #pragma unroll
        for (int c = 0; c < 4; c++)
            acc[c][0] = acc[c][1] = acc[c][2] = acc[c][3] = 0.0f;

        #pragma unroll 1
        for (int cin = 0; cin < 6; cin++) {
            float win[6][6];
            const float* ib = inb + cin * 196;
            #pragma unroll
            for (int rr = 0; rr < 6; rr++) {
                const float2* row = (const float2*)(ib + rr * 14);
                float2 v0 = row[0], v1 = row[1], v2 = row[2];
                win[rr][0] = v0.x; win[rr][1] = v0.y;
                win[rr][2] = v1.x; win[rr][3] = v1.y;
                win[rr][4] = v2.x; win[rr][5] = v2.y;
            }
            const float* wb = w2s + (cq * 6 + cin) * 100;
            #pragma unroll
            for (int k = 0; k < 25; k++) {
                int ky = k / 5, kx = k % 5;
                float4 wv = *(const float4*)(wb + k * 4);
                float wc[4] = {wv.x, wv.y, wv.z, wv.w};
                #pragma unroll
                for (int c = 0; c < 4; c++) {
                    acc[c][0] = fmaf(wc[c], win[ky][kx],         acc[c][0]);
                    acc[c][1] = fmaf(wc[c], win[ky][kx + 1],     acc[c][1]);
                    acc[c][2] = fmaf(wc[c], win[ky + 1][kx],     acc[c][2]);
                    acc[c][3] = fmaf(wc[c], win[ky + 1][kx + 1], acc[c][3]);
                }
            }
        }
        #pragma unroll
        for (int c = 0; c < 4; c++) {
            int co = cq * 4 + c;
            float m = fmaxf(fmaxf(acc[c][0], acc[c][1]), fmaxf(acc[c][2], acc[c][3]));
            h2[g * 400 + co * 25 + p] = fmaxf(m + b2s[co], 0.0f);
        }
    }
    __syncthreads();

    // ---- fc1: thread = (j 0..119, half 0..1); raw weights + XOR sign trick
    if (tid < 240) {
        int half = tid & 1, j = tid >> 1;
        const float* hg = h2 + half * 4 * 400;
        const float* wr = fw1 + j * 400;
        float acc[4] = {0, 0, 0, 0};
        for (int k = 0; k < 400; k += 4) {
            float4 w = __ldg((const float4*)(wr + k));
            unsigned sx = __float_as_uint(w.x) & 0x80000000u;
            unsigned sy = __float_as_uint(w.y) & 0x80000000u;
            unsigned sz = __float_as_uint(w.z) & 0x80000000u;
            unsigned sw = __float_as_uint(w.w) & 0x80000000u;
            #pragma unroll
            for (int i = 0; i < 4; i++) {
                float4 h = *(const float4*)(hg + i * 400 + k);
                acc[i] += __uint_as_float(__float_as_uint(h.x) ^ sx);
                acc[i] += __uint_as_float(__float_as_uint(h.y) ^ sy);
                acc[i] += __uint_as_float(__float_as_uint(h.z) ^ sz);
                acc[i] += __uint_as_float(__float_as_uint(h.w) ^ sw);
            }
        }
        float sc = g_fscale[0];
        float bb = fb1[j];
        #pragma unroll
        for (int i = 0; i < 4; i++)
            a1[(half * 4 + i) * 120 + j] = fmaxf(fmaf(sc, acc[i], bb), 0.0f);
    }
    __syncthreads();

    // ---- fc2: thread = (j 0..83, half 0..1)
    if (tid < 168) {
        int half = tid & 1, j = tid >> 1;
        const float* hg = a1 + half * 4 * 120;
        const float* wr = fw2 + j * 120;
        float acc[4] = {0, 0, 0, 0};
        for (int k = 0; k < 120; k += 4) {
            float4 w = __ldg((const float4*)(wr + k));
            unsigned sx = __float_as_uint(w.x) & 0x80000000u;
            unsigned sy = __float_as_uint(w.y) & 0x80000000u;
            unsigned sz = __float_as_uint(w.z) & 0x80000000u;
            unsigned sw = __float_as_uint(w.w) & 0x80000000u;
            #pragma unroll
            for (int i = 0; i < 4; i++) {
                float4 h = *(const float4*)(hg + i * 120 + k);
                acc[i] += __uint_as_float(__float_as_uint(h.x) ^ sx);
                acc[i] += __uint_as_float(__float_as_uint(h.y) ^ sy);
                acc[i] += __uint_as_float(__float_as_uint(h.z) ^ sz);
                acc[i] += __uint_as_float(__float_as_uint(h.w) ^ sw);
            }
        }
        float sc = g_fscale[1];
        float bb = fb2[j];
        #pragma unroll
        for (int i = 0; i < 4; i++)
            a2[(half * 4 + i) * 84 + j] = fmaxf(fmaf(sc, acc[i], bb), 0.0f);
    }
    __syncthreads();

    // ---- fc3: thread = (g, j)
    if (tid < G * 10) {
        int g = tid / 10, j = tid % 10;
        const float* ag = a2 + g * 84;
        const float* wr = fw3 + j * 84;
        float acc = 0.0f;
        for (int k = 0; k < 84; k += 4) {
            float4 w = __ldg((const float4*)(wr + k));
            float4 h = *(const float4*)(ag + k);
            acc += __uint_as_float(__float_as_uint(h.x) ^ (__float_as_uint(w.x) & 0x80000000u));
            acc += __uint_as_float(__float_as_uint(h.y) ^ (__float_as_uint(w.y) & 0x80000000u));
            acc += __uint_as_float(__float_as_uint(h.z) ^ (__float_as_uint(w.z) & 0x80000000u));
            acc += __uint_as_float(__float_as_uint(h.w) ^ (__float_as_uint(w.w) & 0x80000000u));
        }
        out[(size_t)(img0 + g) * 10 + j] = fmaf(g_fscale[2], acc, fb3[j]);
    }
}

extern "C" void kernel_launch(void* const* d_in, const int* in_sizes, int n_in,
                              void* d_out, int out_size) {
    const float* x   = (const float*)d_in[0];
    const float* w1  = (const float*)d_in[1];
    const float* b1  = (const float*)d_in[2];
    const float* w2  = (const float*)d_in[3];
    const float* b2  = (const float*)d_in[4];
    const float* fw1 = (const float*)d_in[5];
    const float* fb1 = (const float*)d_in[6];
    const float* fw2 = (const float*)d_in[7];
    const float* fb2 = (const float*)d_in[8];
    const float* fw3 = (const float*)d_in[9];
    const float* fb3 = (const float*)d_in[10];
    float* out = (float*)d_out;

    // smem: G*(1176+400+120+84) + 600+2400+6+16 = 17262 floats = 69,048 B
    const int smem_floats = G * (1176 + 400 + 120 + 84) + 600 + 2400 + 6 + 16;
    const int smem_bytes = smem_floats * (int)sizeof(float);
    cudaFuncSetAttribute(fused_kernel, cudaFuncAttributeMaxDynamicSharedMemorySize,
                         smem_bytes);

    binarize_kernel<<<5, 256>>>(w1, w2, fw1, fw2, fw3);
    fused_kernel<<<NBLK, THREADS, smem_bytes>>>(x, fw1, fw2, fw3,
                                                b1, b2, fb1, fb2, fb3, out);
}

// round 15
// speedup vs baseline: 1.9462x; 1.3149x over previous
#include <cuda_runtime.h>
#include <cuda_bf16.h>
#include <cstdint>

#define G 8
#define THREADS 256
#define NBLK (8192 / G)

// conv1 weights (+-scale baked), sign matrices for MMA, scales.
__device__ __align__(16) float g_w1c[3 * 25 * 8];              // [cin][k][c8]
__device__ __align__(16) __nv_bfloat16 g_s2bf[16 * 240];       // conv2 signs [ch][30 combos x 8 taps] (taps5..7 = 0)
__device__ __align__(16) __nv_bfloat16 g_s1bf[120 * 400];      // fc1 signs [j][k]
__device__ float g_cs2;                                        // conv2 scale
__device__ float g_fscale[3];                                  // fc1, fc2, fc3 scales

__global__ void binarize_kernel(const float* __restrict__ w1,
                                const float* __restrict__ w2,
                                const float* __restrict__ fw1,
                                const float* __restrict__ fw2,
                                const float* __restrict__ fw3) {
    __shared__ float red[256];
    int t = threadIdx.x;
    const float* src = nullptr;
    int n = 0;
    switch (blockIdx.x) {
        case 0: src = w1;  n = 450;   break;
        case 1: src = w2;  n = 2400;  break;
        case 2: src = fw1; n = 48000; break;
        case 3: src = fw2; n = 10080; break;
        case 4: src = fw3; n = 840;   break;
    }
    float s = 0.0f;
    for (int i = t; i < n; i += 256) s += fabsf(src[i]);
    red[t] = s;
    __syncthreads();
    for (int o = 128; o > 0; o >>= 1) {
        if (t < o) red[t] += red[t + o];
        __syncthreads();
    }
    float scale = red[0] / (float)n;

    switch (blockIdx.x) {
        case 0:  // w1[o][cin][5][5] -> [cin][k][c8], +-scale baked
            for (int i = t; i < n; i += 256) {
                int o = i / 75, rem = i % 75, cin = rem / 25, k = rem % 25;
                g_w1c[(cin * 25 + k) * 8 + o] = (src[i] >= 0.0f) ? scale : -scale;
            }
            break;
        case 1:  // conv2 signs: [ch][ (cin*5+ky)*8 + kx ], +-1 (taps 5..7 stay 0)
            for (int i = t; i < n; i += 256) {
                int o = i / 150, rem = i % 150, cin = rem / 25, kk = rem % 25;
                int ky = kk / 5, kx = kk % 5;
                g_s2bf[o * 240 + (cin * 5 + ky) * 8 + kx] =
                    __float2bfloat16((src[i] >= 0.0f) ? 1.0f : -1.0f);
            }
            if (t == 0) g_cs2 = scale;
            break;
        case 2:  // fc1 signs [j][k] = sign(fw1), +-1
            for (int i = t; i < n; i += 256)
                g_s1bf[i] = __float2bfloat16((src[i] >= 0.0f) ? 1.0f : -1.0f);
            if (t == 0) g_fscale[0] = scale;
            break;
        case 3: if (t == 0) g_fscale[1] = scale; break;
        case 4: if (t == 0) g_fscale[2] = scale; break;
    }
}

extern __shared__ float smem[];

// ---- conv1 scalar helpers (unchanged from R14) ----
#define CONV1_KY(TOP, BOT, KY)                                                 \
    {                                                                          \
        _Pragma("unroll")                                                      \
        for (int kx = 0; kx < 5; kx++) {                                       \
            const int k = (KY) * 5 + kx;                                       \
            float4 wv = *(const float4*)(wb + k * 8);                          \
            float2 wv2 = *(const float2*)(wb + k * 8 + 4);                     \
            float wc[6] = {wv.x, wv.y, wv.z, wv.w, wv2.x, wv2.y};              \
            _Pragma("unroll")                                                  \
            for (int c = 0; c < 6; c++) {                                      \
                acc[c][0] = fmaf(wc[c], TOP[kx],     acc[c][0]);               \
                acc[c][1] = fmaf(wc[c], TOP[kx + 1], acc[c][1]);               \
                acc[c][2] = fmaf(wc[c], BOT[kx],     acc[c][2]);               \
                acc[c][3] = fmaf(wc[c], BOT[kx + 1], acc[c][3]);               \
            }                                                                  \
        }                                                                      \
    }

#define LOAD_ROW6(DST, PTR)                                                    \
    {                                                                          \
        float2 va = __ldg((const float2*)(PTR));                               \
        float2 vb = __ldg((const float2*)((PTR) + 2));                         \
        float2 vc = __ldg((const float2*)((PTR) + 4));                         \
        DST[0] = va.x; DST[1] = va.y; DST[2] = vb.x;                           \
        DST[3] = vb.y; DST[4] = vc.x; DST[5] = vc.y;                           \
    }

__device__ __forceinline__ void mma_bf16(float* d, uint32_t a0, uint32_t a1,
                                         uint32_t a2, uint32_t a3,
                                         uint32_t b0, uint32_t b1) {
    asm volatile(
        "mma.sync.aligned.m16n8k16.row.col.f32.bf16.bf16.f32 "
        "{%0,%1,%2,%3}, {%4,%5,%6,%7}, {%8,%9}, {%0,%1,%2,%3};"
        : "+f"(d[0]), "+f"(d[1]), "+f"(d[2]), "+f"(d[3])
        : "r"(a0), "r"(a1), "r"(a2), "r"(a3), "r"(b0), "r"(b1));
}

__device__ __forceinline__ uint32_t prmt5432(uint32_t a, uint32_t b) {
    uint32_t r;
    asm("prmt.b32 %0, %1, %2, 0x5432;" : "=r"(r) : "r"(a), "r"(b));
    return r;
}

__device__ __forceinline__ void split_store(__nv_bfloat16* hi, __nv_bfloat16* lo,
                                            int idx, float v) {
    __nv_bfloat16 h = __float2bfloat16(v);
    hi[idx] = h;
    lo[idx] = __float2bfloat16(v - __bfloat162float(h));
}

__global__ void __launch_bounds__(THREADS, 3)
fused_kernel(const float* __restrict__ x,
             const float* __restrict__ fw2, const float* __restrict__ fw3,
             const float* __restrict__ b1, const float* __restrict__ b2,
             const float* __restrict__ fb1, const float* __restrict__ fb2,
             const float* __restrict__ fb3,
             float* __restrict__ out) {
    // smem layout (floats)
    float* const a1   = smem;                 // 960   [img][120]
    float* const a2v  = a1 + 960;             // 672   [img][84]
    float* const w1s  = a2v + 672;            // 600
    float* const b1s  = w1s + 600;            // 8
    float* const b2s  = b1s + 8;              // 16
    float* const h2hi = b2s + 16;             // 1600 (= 3200 bf16 [img][400])
    float* const h2lo = h2hi + 1600;          // 1600
    float* const p1hi = h2lo + 1600;          // 6048 (= 12096 bf16 [img][cin6][14][18])
    float* const p1lo = p1hi + 6048;          // 6048

    __nv_bfloat16* const p1hi_b = (__nv_bfloat16*)p1hi;
    __nv_bfloat16* const p1lo_b = (__nv_bfloat16*)p1lo;
    __nv_bfloat16* const h2hi_b = (__nv_bfloat16*)h2hi;
    __nv_bfloat16* const h2lo_b = (__nv_bfloat16*)h2lo;
    const uint32_t* const p1hi_u = (const uint32_t*)p1hi;
    const uint32_t* const p1lo_u = (const uint32_t*)p1lo;
    const uint32_t* const h2hi_u = (const uint32_t*)h2hi;
    const uint32_t* const h2lo_u = (const uint32_t*)h2lo;
    uint32_t* const p1hi_w = (uint32_t*)p1hi;
    uint32_t* const p1lo_w = (uint32_t*)p1lo;

    const int tid = threadIdx.x;
    const int img0 = blockIdx.x * G;

    for (int i = tid; i < 600; i += THREADS) w1s[i] = g_w1c[i];
    if (tid < 6)  b1s[tid] = b1[tid];
    if (tid < 16) b2s[tid] = b2[tid];
    // zero p1b pad cols 14..17 (so zero-weight taps multiply finite zeros)
    for (int i = tid; i < 672; i += THREADS) {   // 8*6*14 rows
        p1hi_w[i * 9 + 7] = 0u; p1hi_w[i * 9 + 8] = 0u;
        p1lo_w[i * 9 + 7] = 0u; p1lo_w[i * 9 + 8] = 0u;
    }
    __syncthreads();

    // ---- conv1 + relu + pool (scalar) -> p1b bf16 hi/lo, rows padded to 18
    for (int s = tid; s < G * 196; s += THREADS) {
        int g = s / 196, p = s % 196;
        int py = p / 14, px = p % 14;
        const float* xg = x + (size_t)(img0 + g) * 3072 + py * 64 + px * 2;
        float acc[6][4];
        #pragma unroll
        for (int c = 0; c < 6; c++)
            acc[c][0] = acc[c][1] = acc[c][2] = acc[c][3] = 0.0f;

        #pragma unroll 1
        for (int cin = 0; cin < 3; cin++) {
            const float* ib = xg + cin * 1024;
            const float* wb = w1s + cin * 200;
            float rA[6], rB[6];
            LOAD_ROW6(rA, ib);
            LOAD_ROW6(rB, ib + 32);
            CONV1_KY(rA, rB, 0); LOAD_ROW6(rA, ib + 64);
            CONV1_KY(rB, rA, 1); LOAD_ROW6(rB, ib + 96);
            CONV1_KY(rA, rB, 2); LOAD_ROW6(rA, ib + 128);
            CONV1_KY(rB, rA, 3); LOAD_ROW6(rB, ib + 160);
            CONV1_KY(rA, rB, 4);
        }
        #pragma unroll
        for (int c = 0; c < 6; c++) {
            float m = fmaxf(fmaxf(acc[c][0], acc[c][1]), fmaxf(acc[c][2], acc[c][3]));
            float v = fmaxf(m + b1s[c], 0.0f);
            int ridx = ((g * 6 + c) * 14 + py) * 18 + px;
            split_store(p1hi_b, p1lo_b, ridx, v);
        }
    }
    __syncthreads();

    // ---- conv2 + relu + pool via MMA ----
    // D[16ch x pos], A = signs (gmem), B = sliding windows from p1b.
    // Position order: v = quad*2 + dy; even tile ox=2X, odd tile ox=2X+1.
    {
        int wid = tid >> 5, lane = tid & 31;
        int tq = lane >> 2, tr = lane & 3;
        const uint32_t* s2u = (const uint32_t*)g_s2bf;   // [ch][120 u32]

        for (int u = wid; u < 56; u += 8) {
            int img = u / 7, tp = u % 7;
            float de[4] = {0, 0, 0, 0}, dz[4] = {0, 0, 0, 0};

            // this thread's B column position (n = tq)
            int v = tp * 8 + tq;
            int q = v >> 1, dy = v & 1;
            if (q >= 25) { q = 0; dy = 0; }
            int Y = q / 5, X = q % 5;
            int oy = 2 * Y + dy;
            int oxe = 2 * X;

            #pragma unroll
            for (int ks = 0; ks < 15; ks++) {
                const int m0 = 2 * ks, m1 = 2 * ks + 1;
                const int cin0 = m0 / 5, ky0 = m0 % 5;
                const int cin1 = m1 / 5, ky1 = m1 % 5;
                // A: signs [ch][240], pairs at k=16ks+2tr (+8)
                uint32_t A0 = __ldg(s2u + tq * 120 + ks * 8 + tr);
                uint32_t A1 = __ldg(s2u + (tq + 8) * 120 + ks * 8 + tr);
                uint32_t A2 = __ldg(s2u + tq * 120 + ks * 8 + tr + 4);
                uint32_t A3 = __ldg(s2u + (tq + 8) * 120 + ks * 8 + tr + 4);

                int r0 = ((img * 6 + cin0) * 14 + (oy + ky0)) * 18;
                int r1 = ((img * 6 + cin1) * 14 + (oy + ky1)) * 18;
                int ce = oxe + 2 * tr;     // even col base (even)
                uint32_t e0h = p1hi_u[(r0 + ce) >> 1];
                uint32_t e1h = p1hi_u[(r1 + ce) >> 1];
                uint32_t e0l = p1lo_u[(r0 + ce) >> 1];
                uint32_t e1l = p1lo_u[(r1 + ce) >> 1];
                mma_bf16(de, A0, A1, A2, A3, e0h, e1h);
                mma_bf16(de, A0, A1, A2, A3, e0l, e1l);
                // odd tile: cols ce+1 .. : pair = prmt(word(ce), word(ce+2))
                uint32_t x0h = p1hi_u[((r0 + ce) >> 1) + 1];
                uint32_t x1h = p1hi_u[((r1 + ce) >> 1) + 1];
                uint32_t x0l = p1lo_u[((r0 + ce) >> 1) + 1];
                uint32_t x1l = p1lo_u[((r1 + ce) >> 1) + 1];
                uint32_t o0h = prmt5432(e0h, x0h);
                uint32_t o1h = prmt5432(e1h, x1h);
                uint32_t o0l = prmt5432(e0l, x0l);
                uint32_t o1l = prmt5432(e1l, x1l);
                mma_bf16(dz, A0, A1, A2, A3, o0h, o1h);
                mma_bf16(dz, A0, A1, A2, A3, o0l, o1l);
            }

            // D cols 2tr,2tr+1 = vertical pair of quad qq = tp*4+tr;
            // horizontal = even vs odd tile elementwise.
            int qq = tp * 4 + tr;
            if (qq < 25) {
                float sc = g_cs2;
                float m0 = fmaxf(fmaxf(de[0], de[1]), fmaxf(dz[0], dz[1])); // ch=tq
                float m1 = fmaxf(fmaxf(de[2], de[3]), fmaxf(dz[2], dz[3])); // ch=tq+8
                float h0 = fmaxf(fmaf(sc, m0, b2s[tq]), 0.0f);
                float h1 = fmaxf(fmaf(sc, m1, b2s[tq + 8]), 0.0f);
                split_store(h2hi_b, h2lo_b, img * 400 + tq * 25 + qq, h0);
                split_store(h2hi_b, h2lo_b, img * 400 + (tq + 8) * 25 + qq, h1);
            }
        }
    }
    __syncthreads();

    // ---- fc1 via MMA: D[8img x 120], A = h2b hi/lo, B = signs [j][400] ----
    {
        int wid = tid >> 5, lane = tid & 31;
        int tq = lane >> 2, tr = lane & 3;
        const uint32_t* s1u = (const uint32_t*)g_s1bf;   // [j][200 u32]

        for (int nt = wid; nt < 15; nt += 8) {
            float d[4] = {0, 0, 0, 0};
            int j = nt * 8 + tq;   // B column
            #pragma unroll 5
            for (int ks = 0; ks < 25; ks++) {
                uint32_t a0 = h2hi_u[tq * 200 + ks * 8 + tr];
                uint32_t a2 = h2hi_u[tq * 200 + ks * 8 + tr + 4];
                uint32_t l0 = h2lo_u[tq * 200 + ks * 8 + tr];
                uint32_t l2 = h2lo_u[tq * 200 + ks * 8 + tr + 4];
                uint32_t B0 = __ldg(s1u + j * 200 + ks * 8 + tr);
                uint32_t B1 = __ldg(s1u + j * 200 + ks * 8 + tr + 4);
                mma_bf16(d, a0, 0u, a2, 0u, B0, B1);
                mma_bf16(d, l0, 0u, l2, 0u, B0, B1);
            }
            // D: row tq = img, cols nt*8 + 2tr (+1); rows tq+8 discarded
            int jc = nt * 8 + 2 * tr;
            float sc = g_fscale[0];
            a1[tq * 120 + jc]     = fmaxf(fmaf(sc, d[0], __ldg(fb1 + jc)), 0.0f);
            a1[tq * 120 + jc + 1] = fmaxf(fmaf(sc, d[1], __ldg(fb1 + jc + 1)), 0.0f);
        }
    }
    __syncthreads();

    // ---- fc2 scalar XOR: thread = (j 0..83, half 0..1) ----
    if (tid < 168) {
        int half = tid & 1, j = tid >> 1;
        const float* hg = a1 + half * 4 * 120;
        const float* wr = fw2 + j * 120;
        float acc[4] = {0, 0, 0, 0};
        for (int k = 0; k < 120; k += 4) {
            float4 w = __ldg((const float4*)(wr + k));
            unsigned sx = __float_as_uint(w.x) & 0x80000000u;
            unsigned sy = __float_as_uint(w.y) & 0x80000000u;
            unsigned sz = __float_as_uint(w.z) & 0x80000000u;
            unsigned sw = __float_as_uint(w.w) & 0x80000000u;
            #pragma unroll
            for (int i = 0; i < 4; i++) {
                float4 h = *(const float4*)(hg + i * 120 + k);
                acc[i] += __uint_as_float(__float_as_uint(h.x) ^ sx);
                acc[i] += __uint_as_float(__float_as_uint(h.y) ^ sy);
                acc[i] += __uint_as_float(__float_as_uint(h.z) ^ sz);
                acc[i] += __uint_as_float(__float_as_uint(h.w) ^ sw);
            }
        }
        float sc = g_fscale[1];
        float bb = fb2[j];
        #pragma unroll
        for (int i = 0; i < 4; i++)
            a2v[(half * 4 + i) * 84 + j] = fmaxf(fmaf(sc, acc[i], bb), 0.0f);
    }
    __syncthreads();

    // ---- fc3 scalar XOR ----
    if (tid < G * 10) {
        int g = tid / 10, j = tid % 10;
        const float* ag = a2v + g * 84;
        const float* wr = fw3 + j * 84;
        float acc = 0.0f;
        for (int k = 0; k < 84; k += 4) {
            float4 w = __ldg((const float4*)(wr + k));
            float4 h = *(const float4*)(ag + k);
            acc += __uint_as_float(__float_as_uint(h.x) ^ (__float_as_uint(w.x) & 0x80000000u));
            acc += __uint_as_float(__float_as_uint(h.y) ^ (__float_as_uint(w.y) & 0x80000000u));
            acc += __uint_as_float(__float_as_uint(h.z) ^ (__float_as_uint(w.z) & 0x80000000u));
            acc += __uint_as_float(__float_as_uint(h.w) ^ (__float_as_uint(w.w) & 0x80000000u));
        }
        out[(size_t)(img0 + g) * 10 + j] = fmaf(g_fscale[2], acc, fb3[j]);
    }
}

extern "C" void kernel_launch(void* const* d_in, const int* in_sizes, int n_in,
                              void* d_out, int out_size) {
    const float* x   = (const float*)d_in[0];
    const float* w1  = (const float*)d_in[1];
    const float* b1  = (const float*)d_in[2];
    const float* w2  = (const float*)d_in[3];
    const float* b2  = (const float*)d_in[4];
    const float* fw1 = (const float*)d_in[5];
    const float* fb1 = (const float*)d_in[6];
    const float* fw2 = (const float*)d_in[7];
    const float* fb2 = (const float*)d_in[8];
    const float* fw3 = (const float*)d_in[9];
    const float* fb3 = (const float*)d_in[10];
    float* out = (float*)d_out;

    // smem: 960+672+600+8+16+1600+1600+6048+6048 = 17552 floats = 70,208 B
    const int smem_bytes = 17552 * (int)sizeof(float);
    cudaFuncSetAttribute(fused_kernel, cudaFuncAttributeMaxDynamicSharedMemorySize,
                         smem_bytes);

    binarize_kernel<<<5, 256>>>(w1, w2, fw1, fw2, fw3);
    fused_kernel<<<NBLK, THREADS, smem_bytes>>>(x, fw2, fw3,
                                                b1, b2, fb1, fb2, fb3, out);
}